// round 1
// baseline (speedup 1.0000x reference)
#include <cuda_runtime.h>
#include <math.h>

// ---------------------------------------------------------------------------
// Fused MildenhallNeRF forward:
//   hash_encode (16 levels, trilinear, T=16384, F=2)
//   -> relu(feat @ dW0 + db0) @ dW1 + db1
//   -> density = sigmoid(h[0]); h_rest = relu(h[1:16])
//   -> c = [density, h_rest, view]  (19)
//   -> relu(c@cW0+cb0) -> relu(@cW1+cb1) -> sigmoid(@cW2+cb2)
//   out = [density, color]  (B,4) fp32
// One thread per point. All weights staged in static shared memory.
// ---------------------------------------------------------------------------

namespace {

constexpr int L_LEVELS = 16;
constexpr int T_SIZE   = 16384;
constexpr int NTHREADS = 128;

struct NsParams { int ns[L_LEVELS]; };

__global__ __launch_bounds__(NTHREADS, 3)
void nerf_fused_kernel(const float* __restrict__ x,
                       const float* __restrict__ embed,
                       const float* __restrict__ dW0, const float* __restrict__ db0,
                       const float* __restrict__ dW1, const float* __restrict__ db1,
                       const float* __restrict__ cW0, const float* __restrict__ cb0,
                       const float* __restrict__ cW1, const float* __restrict__ cb1,
                       const float* __restrict__ cW2, const float* __restrict__ cb2,
                       float* __restrict__ out, int B, NsParams nsp)
{
    // ---- stage all weights/biases into shared memory (~35 KB) ----
    __shared__ float sW0[32 * 64];
    __shared__ float sB0[64];
    __shared__ float sW1[64 * 16];
    __shared__ float sB1[16];
    __shared__ float sC0W[19 * 64];
    __shared__ float sC0B[64];
    __shared__ float sC1W[64 * 64];
    __shared__ float sC1B[64];
    __shared__ float sC2W[64 * 3];
    __shared__ float sC2B[3];

    const int tid = threadIdx.x;
    for (int i = tid; i < 32 * 64; i += NTHREADS) sW0[i]  = dW0[i];
    for (int i = tid; i < 64 * 16; i += NTHREADS) sW1[i]  = dW1[i];
    for (int i = tid; i < 19 * 64; i += NTHREADS) sC0W[i] = cW0[i];
    for (int i = tid; i < 64 * 64; i += NTHREADS) sC1W[i] = cW1[i];
    for (int i = tid; i < 64 * 3;  i += NTHREADS) sC2W[i] = cW2[i];
    for (int i = tid; i < 64; i += NTHREADS) {
        sB0[i]  = db0[i];
        sC0B[i] = cb0[i];
        sC1B[i] = cb1[i];
    }
    if (tid < 16) sB1[tid]  = db1[tid];
    if (tid < 3)  sC2B[tid] = cb2[tid];
    __syncthreads();

    const int gi = blockIdx.x * NTHREADS + tid;
    if (gi >= B) return;

    // ---- load point (x,y,z) and view direction ----
    const float2* xv = reinterpret_cast<const float2*>(x) + (size_t)gi * 3;
    const float2 a0 = xv[0];
    const float2 a1 = xv[1];
    const float2 a2 = xv[2];
    float px = a0.x, py = a0.y, pz = a1.x;
    const float vx = a1.y, vy = a2.x, vz = a2.y;

    // scaled = (x - BB_MIN)/BB_SIZE, clipped to [0, 1-1e-6]
    px = fminf(fmaxf((px + 5.0f) / 10.0f, 0.0f), 0.999999f);
    py = fminf(fmaxf((py + 5.0f) / 10.0f, 0.0f), 0.999999f);
    pz = fminf(fmaxf((pz + 5.0f) / 10.0f, 0.0f), 0.999999f);

    // ---- hidden accumulator: h = db0, accumulate feat @ dW0 level-by-level ----
    float h[64];
#pragma unroll
    for (int j = 0; j < 64; j++) h[j] = sB0[j];

    for (int l = 0; l < L_LEVELS; l++) {
        const int   n  = nsp.ns[l];
        const float nf = (float)n;

        const float xl0 = px * nf, xl1 = py * nf, xl2 = pz * nf;
        const float f0 = floorf(xl0), f1 = floorf(xl1), f2 = floorf(xl2);
        const float w0 = xl0 - f0, w1 = xl1 - f1, w2 = xl2 - f2;
        const float u0 = 1.0f - w0, u1 = 1.0f - w1, u2 = 1.0f - w2;
        const int v0 = (int)f0, v1 = (int)f1, v2 = (int)f2;

        const int  np1   = n + 1;
        const bool dense = (np1 * np1 * np1 <= T_SIZE);

        const float2* tab = reinterpret_cast<const float2*>(embed) + (size_t)l * T_SIZE;

        float acc0 = 0.0f, acc1 = 0.0f;
#pragma unroll
        for (int c = 0; c < 8; c++) {
            const int bx = (c >> 2) & 1;   // dim0 offset
            const int by = (c >> 1) & 1;   // dim1 offset
            const int bz =  c       & 1;   // dim2 offset
            const int ux = v0 + bx, uy = v1 + by, uz = v2 + bz;

            int idx;
            if (dense) {
                idx = (ux * np1 + uy) * np1 + uz;
            } else {
                const unsigned hsh = (unsigned)ux
                                   ^ ((unsigned)uy * 2654435761u)
                                   ^ ((unsigned)uz * 805459861u);
                idx = (int)(hsh & (unsigned)(T_SIZE - 1));
            }

            const float wgt = (bx ? w0 : u0) * (by ? w1 : u1) * (bz ? w2 : u2);
            const float2 ft = __ldg(&tab[idx]);
            acc0 = fmaf(wgt, ft.x, acc0);
            acc1 = fmaf(wgt, ft.y, acc1);
        }

        const float* r0 = &sW0[(2 * l)     * 64];
        const float* r1 = &sW0[(2 * l + 1) * 64];
#pragma unroll
        for (int j = 0; j < 64; j++) {
            h[j] = fmaf(acc0, r0[j], h[j]);
            h[j] = fmaf(acc1, r1[j], h[j]);
        }
    }

    // ---- layer 1: h2 = relu(h) @ dW1 + db1   (64 -> 16) ----
    float h2[16];
#pragma unroll
    for (int m = 0; m < 16; m++) h2[m] = sB1[m];
#pragma unroll
    for (int j = 0; j < 64; j++) {
        const float hj = fmaxf(h[j], 0.0f);
        const float* wr = &sW1[j * 16];
#pragma unroll
        for (int m = 0; m < 16; m++) h2[m] = fmaf(hj, wr[m], h2[m]);
    }

    const float density = 1.0f / (1.0f + expf(-h2[0]));

    // ---- c_in = [density, relu(h2[1:16]), view]  (19) ----
    float cin[19];
    cin[0] = density;
#pragma unroll
    for (int m = 1; m < 16; m++) cin[m] = fmaxf(h2[m], 0.0f);
    cin[16] = vx; cin[17] = vy; cin[18] = vz;

    // ---- c1 = relu(c_in @ cW0 + cb0)   (19 -> 64) ----
    float c1[64];
#pragma unroll
    for (int j = 0; j < 64; j++) c1[j] = sC0B[j];
#pragma unroll
    for (int k = 0; k < 19; k++) {
        const float ck = cin[k];
        const float* wr = &sC0W[k * 64];
#pragma unroll
        for (int j = 0; j < 64; j++) c1[j] = fmaf(ck, wr[j], c1[j]);
    }
#pragma unroll
    for (int j = 0; j < 64; j++) c1[j] = fmaxf(c1[j], 0.0f);

    // ---- c2 = relu(c1 @ cW1 + cb1) streamed straight into cW2 (64 -> 64 -> 3) ----
    float col0 = sC2B[0], col1 = sC2B[1], col2 = sC2B[2];
#pragma unroll
    for (int j = 0; j < 64; j++) {
        float a = sC1B[j];
#pragma unroll
        for (int k = 0; k < 64; k++) a = fmaf(c1[k], sC1W[k * 64 + j], a);
        a = fmaxf(a, 0.0f);
        col0 = fmaf(a, sC2W[j * 3 + 0], col0);
        col1 = fmaf(a, sC2W[j * 3 + 1], col1);
        col2 = fmaf(a, sC2W[j * 3 + 2], col2);
    }

    const float r = 1.0f / (1.0f + expf(-col0));
    const float g = 1.0f / (1.0f + expf(-col1));
    const float b = 1.0f / (1.0f + expf(-col2));

    reinterpret_cast<float4*>(out)[gi] = make_float4(density, r, g, b);
}

} // anonymous namespace

extern "C" void kernel_launch(void* const* d_in, const int* in_sizes, int n_in,
                              void* d_out, int out_size)
{
    const float* x    = (const float*)d_in[0];
    const float* emb  = (const float*)d_in[1];
    const float* dW0  = (const float*)d_in[2];
    const float* db0  = (const float*)d_in[3];
    const float* dW1  = (const float*)d_in[4];
    const float* db1  = (const float*)d_in[5];
    const float* cW0  = (const float*)d_in[6];
    const float* cb0  = (const float*)d_in[7];
    const float* cW1  = (const float*)d_in[8];
    const float* cb1  = (const float*)d_in[9];
    const float* cW2  = (const float*)d_in[10];
    const float* cb2  = (const float*)d_in[11];
    float* out = (float*)d_out;

    const int B = in_sizes[0] / 6;

    // NS[l] = int(16 * exp((log 512 - log 16)/15)^l), exact numpy semantics
    NsParams nsp;
    const double g = exp((log(512.0) - log(16.0)) / 15.0);
    for (int i = 0; i < L_LEVELS; i++) {
        nsp.ns[i] = (int)(16.0 * pow(g, (double)i));
    }

    const int grid = (B + NTHREADS - 1) / NTHREADS;
    nerf_fused_kernel<<<grid, NTHREADS>>>(x, emb, dW0, db0, dW1, db1,
                                          cW0, cb0, cW1, cb1, cW2, cb2,
                                          out, B, nsp);
}

// round 2
// speedup vs baseline: 1.0551x; 1.0551x over previous
#include <cuda_runtime.h>
#include <math.h>

// ---------------------------------------------------------------------------
// Fused MildenhallNeRF forward, round 2:
//  - packed fma.rn.f32x2 (FFMA2) for all MLP loops (halves FMA instr count)
//  - all SMEM weight reads widened to 64/128-bit (quarters LDS count)
//  - cW1 staged transposed so k-pairs are contiguous for packed accumulation
// ---------------------------------------------------------------------------

namespace {

constexpr int L_LEVELS = 16;
constexpr int T_SIZE   = 16384;
constexpr int NTHREADS = 128;

typedef unsigned long long u64;

struct NsParams { int ns[L_LEVELS]; };

__device__ __forceinline__ void fma2(u64& d, u64 a, u64 b) {
    asm("fma.rn.f32x2 %0, %1, %2, %0;" : "+l"(d) : "l"(a), "l"(b));
}
__device__ __forceinline__ u64 pack2(float lo, float hi) {
    u64 r; asm("mov.b64 %0, {%1, %2};" : "=l"(r) : "f"(lo), "f"(hi)); return r;
}
__device__ __forceinline__ float2 unpack2(u64 v) {
    float2 r; asm("mov.b64 {%0, %1}, %2;" : "=f"(r.x), "=f"(r.y) : "l"(v)); return r;
}
__device__ __forceinline__ float sigmoidf_fast(float v) {
    return 1.0f / (1.0f + __expf(-v));
}

__global__ __launch_bounds__(NTHREADS, 3)
void nerf_fused_kernel(const float* __restrict__ x,
                       const float* __restrict__ embed,
                       const float* __restrict__ dW0, const float* __restrict__ db0,
                       const float* __restrict__ dW1, const float* __restrict__ db1,
                       const float* __restrict__ cW0, const float* __restrict__ cb0,
                       const float* __restrict__ cW1, const float* __restrict__ cb1,
                       const float* __restrict__ cW2, const float* __restrict__ cb2,
                       float* __restrict__ out, int B, NsParams nsp)
{
    // ---- stage weights/biases in shared memory (16B aligned for wide LDS) ----
    __shared__ alignas(16) float sW0 [32 * 64];
    __shared__ alignas(16) float sB0 [64];
    __shared__ alignas(16) float sW1 [64 * 16];
    __shared__ alignas(16) float sB1 [16];
    __shared__ alignas(16) float sC0W[20 * 64];      // 19 rows used
    __shared__ alignas(16) float sC0B[64];
    __shared__ alignas(16) float sC1Wt[64 * 64];     // TRANSPOSED: [j][k]
    __shared__ alignas(16) float sC1B[64];
    __shared__ alignas(16) float sC2W[64 * 4];       // padded rows of 4: [j][{0,1,2,pad}]
    __shared__ alignas(16) float sC2B[4];

    const int tid = threadIdx.x;
    for (int i = tid; i < 32 * 64; i += NTHREADS) sW0[i]  = dW0[i];
    for (int i = tid; i < 64 * 16; i += NTHREADS) sW1[i]  = dW1[i];
    for (int i = tid; i < 19 * 64; i += NTHREADS) sC0W[i] = cW0[i];
    for (int i = tid; i < 64 * 64; i += NTHREADS) {
        const int k = i >> 6, j = i & 63;
        sC1Wt[j * 64 + k] = cW1[i];
    }
    for (int i = tid; i < 64; i += NTHREADS) {
        sB0[i]  = db0[i];
        sC0B[i] = cb0[i];
        sC1B[i] = cb1[i];
        sC2W[i * 4 + 0] = cW2[i * 3 + 0];
        sC2W[i * 4 + 1] = cW2[i * 3 + 1];
        sC2W[i * 4 + 2] = cW2[i * 3 + 2];
        sC2W[i * 4 + 3] = 0.0f;
    }
    if (tid < 16) sB1[tid]  = db1[tid];
    if (tid < 4)  sC2B[tid] = (tid < 3) ? cb2[tid] : 0.0f;
    __syncthreads();

    const int gi = blockIdx.x * NTHREADS + tid;
    if (gi >= B) return;

    // ---- load point + view ----
    const float2* xv = reinterpret_cast<const float2*>(x) + (size_t)gi * 3;
    const float2 a0 = xv[0];
    const float2 a1 = xv[1];
    const float2 a2 = xv[2];
    float px = a0.x, py = a0.y, pz = a1.x;
    const float vx = a1.y, vy = a2.x, vz = a2.y;

    px = fminf(fmaxf((px + 5.0f) * 0.1f, 0.0f), 0.999999f);
    py = fminf(fmaxf((py + 5.0f) * 0.1f, 0.0f), 0.999999f);
    pz = fminf(fmaxf((pz + 5.0f) * 0.1f, 0.0f), 0.999999f);

    // ---- h = db0; accumulate hash features @ dW0, packed ----
    u64 hp[32];
    {
        const u64* b = reinterpret_cast<const u64*>(sB0);
#pragma unroll
        for (int j = 0; j < 32; j++) hp[j] = b[j];
    }

    for (int l = 0; l < L_LEVELS; l++) {
        const int   n  = nsp.ns[l];
        const float nf = (float)n;

        const float xl0 = px * nf, xl1 = py * nf, xl2 = pz * nf;
        const float f0 = floorf(xl0), f1 = floorf(xl1), f2 = floorf(xl2);
        const float w0 = xl0 - f0, w1 = xl1 - f1, w2 = xl2 - f2;
        const float u0 = 1.0f - w0, u1 = 1.0f - w1, u2 = 1.0f - w2;
        const int v0 = (int)f0, v1 = (int)f1, v2 = (int)f2;

        const int  np1   = n + 1;
        const bool dense = (np1 * np1 * np1 <= T_SIZE);

        const float2* tab = reinterpret_cast<const float2*>(embed) + (size_t)l * T_SIZE;

        // trilinear corner weights: 4 + 8 muls
        const float q00 = u1 * u2, q01 = u1 * w2, q10 = w1 * u2, q11 = w1 * w2;
        float wgt[8];
        wgt[0] = u0 * q00; wgt[1] = u0 * q01; wgt[2] = u0 * q10; wgt[3] = u0 * q11;
        wgt[4] = w0 * q00; wgt[5] = w0 * q01; wgt[6] = w0 * q10; wgt[7] = w0 * q11;

        int idx[8];
        if (dense) {
            const int base = (v0 * np1 + v1) * np1 + v2;
            const int sx = np1 * np1;
            idx[0] = base;            idx[1] = base + 1;
            idx[2] = base + np1;      idx[3] = base + np1 + 1;
            idx[4] = base + sx;       idx[5] = base + sx + 1;
            idx[6] = base + sx + np1; idx[7] = base + sx + np1 + 1;
        } else {
            const unsigned t1  = (unsigned)v1 * 2654435761u;
            const unsigned t1b = t1 + 2654435761u;
            const unsigned t2  = (unsigned)v2 * 805459861u;
            const unsigned t2b = t2 + 805459861u;
            const unsigned x0  = (unsigned)v0;
            const unsigned x0b = x0 + 1u;
            const unsigned m   = (unsigned)(T_SIZE - 1);
            idx[0] = (int)((x0  ^ t1  ^ t2 ) & m);
            idx[1] = (int)((x0  ^ t1  ^ t2b) & m);
            idx[2] = (int)((x0  ^ t1b ^ t2 ) & m);
            idx[3] = (int)((x0  ^ t1b ^ t2b) & m);
            idx[4] = (int)((x0b ^ t1  ^ t2 ) & m);
            idx[5] = (int)((x0b ^ t1  ^ t2b) & m);
            idx[6] = (int)((x0b ^ t1b ^ t2 ) & m);
            idx[7] = (int)((x0b ^ t1b ^ t2b) & m);
        }

        float acc0 = 0.0f, acc1 = 0.0f;
#pragma unroll
        for (int c = 0; c < 8; c++) {
            const float2 ft = __ldg(&tab[idx[c]]);
            acc0 = fmaf(wgt[c], ft.x, acc0);
            acc1 = fmaf(wgt[c], ft.y, acc1);
        }

        const u64 a0p = pack2(acc0, acc0);
        const u64 a1p = pack2(acc1, acc1);
        const u64* r0 = reinterpret_cast<const u64*>(&sW0[(2 * l) * 64]);       // 32 u64
        const u64* r1 = reinterpret_cast<const u64*>(&sW0[(2 * l + 1) * 64]);
#pragma unroll
        for (int j = 0; j < 32; j++) {
            fma2(hp[j], a0p, r0[j]);
            fma2(hp[j], a1p, r1[j]);
        }
    }

    // ---- layer 1: h2 = relu(h) @ dW1 + db1  (64 -> 16), packed over m ----
    u64 hq[8];
    {
        const u64* b = reinterpret_cast<const u64*>(sB1);
#pragma unroll
        for (int m = 0; m < 8; m++) hq[m] = b[m];
    }
#pragma unroll
    for (int j2 = 0; j2 < 32; j2++) {
        const float2 hv = unpack2(hp[j2]);
        const float h0 = fmaxf(hv.x, 0.0f);
        const float h1 = fmaxf(hv.y, 0.0f);
        const u64 h0p = pack2(h0, h0);
        const u64 h1p = pack2(h1, h1);
        const u64* w0 = reinterpret_cast<const u64*>(&sW1[(2 * j2) * 16]);   // 8 u64
        const u64* w1 = reinterpret_cast<const u64*>(&sW1[(2 * j2 + 1) * 16]);
#pragma unroll
        for (int m = 0; m < 8; m++) {
            fma2(hq[m], h0p, w0[m]);
            fma2(hq[m], h1p, w1[m]);
        }
    }

    float h2[16];
#pragma unroll
    for (int m = 0; m < 8; m++) {
        const float2 v = unpack2(hq[m]);
        h2[2 * m] = v.x; h2[2 * m + 1] = v.y;
    }

    const float density = sigmoidf_fast(h2[0]);

    // ---- cin = [density, relu(h2[1:16]), view]  (19) ----
    float cin[19];
    cin[0] = density;
#pragma unroll
    for (int m = 1; m < 16; m++) cin[m] = fmaxf(h2[m], 0.0f);
    cin[16] = vx; cin[17] = vy; cin[18] = vz;

    // ---- c1 = relu(cin @ cW0 + cb0)  (19 -> 64), packed over j ----
    u64 c1p[32];
    {
        const u64* b = reinterpret_cast<const u64*>(sC0B);
#pragma unroll
        for (int j = 0; j < 32; j++) c1p[j] = b[j];
    }
#pragma unroll
    for (int k = 0; k < 19; k++) {
        const u64 ckp = pack2(cin[k], cin[k]);
        const u64* wr = reinterpret_cast<const u64*>(&sC0W[k * 64]);   // 32 u64
#pragma unroll
        for (int j = 0; j < 32; j++) fma2(c1p[j], ckp, wr[j]);
    }
#pragma unroll
    for (int j = 0; j < 32; j++) {
        float2 v = unpack2(c1p[j]);
        v.x = fmaxf(v.x, 0.0f);
        v.y = fmaxf(v.y, 0.0f);
        c1p[j] = pack2(v.x, v.y);
    }

    // ---- c2 = relu(c1 @ cW1 + cb1) streamed into cW2 (64 -> 64 -> 3) ----
    // cW1 is transposed in SMEM: row j holds the 64 k-weights contiguously.
    float col0 = sC2B[0], col1 = sC2B[1], col2 = sC2B[2];
#pragma unroll 4
    for (int j = 0; j < 64; j++) {
        u64 ap = 0ULL;   // packed (0,0)
        const u64* wr = reinterpret_cast<const u64*>(&sC1Wt[j * 64]);  // 32 u64
#pragma unroll
        for (int k = 0; k < 32; k++) fma2(ap, c1p[k], wr[k]);
        const float2 v = unpack2(ap);
        float a = sC1B[j] + v.x + v.y;
        a = fmaxf(a, 0.0f);
        const float4 w2v = *reinterpret_cast<const float4*>(&sC2W[j * 4]);
        col0 = fmaf(a, w2v.x, col0);
        col1 = fmaf(a, w2v.y, col1);
        col2 = fmaf(a, w2v.z, col2);
    }

    const float r = sigmoidf_fast(col0);
    const float g = sigmoidf_fast(col1);
    const float b = sigmoidf_fast(col2);

    reinterpret_cast<float4*>(out)[gi] = make_float4(density, r, g, b);
}

} // anonymous namespace

extern "C" void kernel_launch(void* const* d_in, const int* in_sizes, int n_in,
                              void* d_out, int out_size)
{
    const float* x    = (const float*)d_in[0];
    const float* emb  = (const float*)d_in[1];
    const float* dW0  = (const float*)d_in[2];
    const float* db0  = (const float*)d_in[3];
    const float* dW1  = (const float*)d_in[4];
    const float* db1  = (const float*)d_in[5];
    const float* cW0  = (const float*)d_in[6];
    const float* cb0  = (const float*)d_in[7];
    const float* cW1  = (const float*)d_in[8];
    const float* cb1  = (const float*)d_in[9];
    const float* cW2  = (const float*)d_in[10];
    const float* cb2  = (const float*)d_in[11];
    float* out = (float*)d_out;

    const int B = in_sizes[0] / 6;

    NsParams nsp;
    const double g = exp((log(512.0) - log(16.0)) / 15.0);
    for (int i = 0; i < L_LEVELS; i++) {
        nsp.ns[i] = (int)(16.0 * pow(g, (double)i));
    }

    const int grid = (B + NTHREADS - 1) / NTHREADS;
    nerf_fused_kernel<<<grid, NTHREADS>>>(x, emb, dW0, db0, dW1, db1,
                                          cW0, cb0, cW1, cb1, cW2, cb2,
                                          out, B, nsp);
}

// round 3
// speedup vs baseline: 1.6887x; 1.6005x over previous
#include <cuda_runtime.h>
#include <math.h>

// ---------------------------------------------------------------------------
// Round 3: two-phase.
//  Phase 1 (gather): one CTA per (level, point-chunk); the level's full
//    16384x2 f32 table lives in SMEM, so corner gathers are LDS (no 32-line
//    LDG wavefronts). Writes features feature-major to __device__ scratch.
//  Phase 2 (MLP): fused dense layers, 2 points/thread so every broadcast
//    weight LDS feeds two packed fma.rn.f32x2.
// ---------------------------------------------------------------------------

namespace {

constexpr int L_LEVELS = 16;
constexpr int T_SIZE   = 16384;
constexpr int B_MAX    = 1 << 21;            // 2,097,152
constexpr int P1_THREADS = 1024;
constexpr int P1_PTS_PER_BLOCK = 16384;
constexpr int P2_THREADS = 128;
constexpr int P2_PTS_PER_THREAD = 2;

typedef unsigned long long u64;

struct NsParams { int ns[L_LEVELS]; };

__device__ float2 g_feats[(size_t)L_LEVELS * B_MAX];   // 256 MB scratch

__device__ __forceinline__ void fma2(u64& d, u64 a, u64 b) {
    asm("fma.rn.f32x2 %0, %1, %2, %0;" : "+l"(d) : "l"(a), "l"(b));
}
__device__ __forceinline__ u64 pack2(float lo, float hi) {
    u64 r; asm("mov.b64 %0, {%1, %2};" : "=l"(r) : "f"(lo), "f"(hi)); return r;
}
__device__ __forceinline__ float2 unpack2(u64 v) {
    float2 r; asm("mov.b64 {%0, %1}, %2;" : "=f"(r.x), "=f"(r.y) : "l"(v)); return r;
}
__device__ __forceinline__ float sigmoidf_fast(float v) {
    return 1.0f / (1.0f + __expf(-v));
}

// ============================ Phase 1: gather ==============================
__global__ __launch_bounds__(P1_THREADS, 1)
void gather_kernel(const float* __restrict__ x,
                   const float* __restrict__ embed,
                   int B, NsParams nsp)
{
    extern __shared__ float2 stab[];   // T_SIZE float2 = 128 KB

    const int l = blockIdx.y;
    const int n = nsp.ns[l];
    const float nf = (float)n;
    const int np1 = n + 1;
    const bool dense = (np1 * np1 * np1 <= T_SIZE);

    // stage this level's table into SMEM (coalesced float4)
    {
        const float4* src = reinterpret_cast<const float4*>(embed) + (size_t)l * (T_SIZE / 2);
        float4* dst = reinterpret_cast<float4*>(stab);
        for (int i = threadIdx.x; i < T_SIZE / 2; i += P1_THREADS) dst[i] = src[i];
    }
    __syncthreads();

    const int base = blockIdx.x * P1_PTS_PER_BLOCK;
    const int end  = min(base + P1_PTS_PER_BLOCK, B);
    float2* featl = g_feats + (size_t)l * B;

    for (int p = base + threadIdx.x; p < end; p += P1_THREADS) {
        // x layout [p][6]; read first 3 floats via two aligned float2 loads
        const float2* xv = reinterpret_cast<const float2*>(x) + (size_t)p * 3;
        const float2 a0 = __ldg(&xv[0]);
        const float2 a1 = __ldg(&xv[1]);

        float px = fminf(fmaxf((a0.x + 5.0f) * 0.1f, 0.0f), 0.999999f);
        float py = fminf(fmaxf((a0.y + 5.0f) * 0.1f, 0.0f), 0.999999f);
        float pz = fminf(fmaxf((a1.x + 5.0f) * 0.1f, 0.0f), 0.999999f);

        const float xl0 = px * nf, xl1 = py * nf, xl2 = pz * nf;
        const float f0 = floorf(xl0), f1 = floorf(xl1), f2 = floorf(xl2);
        const float w0 = xl0 - f0, w1 = xl1 - f1, w2 = xl2 - f2;
        const float u0 = 1.0f - w0, u1 = 1.0f - w1, u2 = 1.0f - w2;
        const int v0 = (int)f0, v1 = (int)f1, v2 = (int)f2;

        const float q00 = u1 * u2, q01 = u1 * w2, q10 = w1 * u2, q11 = w1 * w2;
        float wgt[8];
        wgt[0] = u0 * q00; wgt[1] = u0 * q01; wgt[2] = u0 * q10; wgt[3] = u0 * q11;
        wgt[4] = w0 * q00; wgt[5] = w0 * q01; wgt[6] = w0 * q10; wgt[7] = w0 * q11;

        int idx[8];
        if (dense) {
            const int bidx = (v0 * np1 + v1) * np1 + v2;
            const int sx = np1 * np1;
            idx[0] = bidx;            idx[1] = bidx + 1;
            idx[2] = bidx + np1;      idx[3] = bidx + np1 + 1;
            idx[4] = bidx + sx;       idx[5] = bidx + sx + 1;
            idx[6] = bidx + sx + np1; idx[7] = bidx + sx + np1 + 1;
        } else {
            const unsigned t1  = (unsigned)v1 * 2654435761u;
            const unsigned t1b = t1 + 2654435761u;
            const unsigned t2  = (unsigned)v2 * 805459861u;
            const unsigned t2b = t2 + 805459861u;
            const unsigned x0  = (unsigned)v0;
            const unsigned x0b = x0 + 1u;
            const unsigned m   = (unsigned)(T_SIZE - 1);
            idx[0] = (int)((x0  ^ t1  ^ t2 ) & m);
            idx[1] = (int)((x0  ^ t1  ^ t2b) & m);
            idx[2] = (int)((x0  ^ t1b ^ t2 ) & m);
            idx[3] = (int)((x0  ^ t1b ^ t2b) & m);
            idx[4] = (int)((x0b ^ t1  ^ t2 ) & m);
            idx[5] = (int)((x0b ^ t1  ^ t2b) & m);
            idx[6] = (int)((x0b ^ t1b ^ t2 ) & m);
            idx[7] = (int)((x0b ^ t1b ^ t2b) & m);
        }

        float acc0 = 0.0f, acc1 = 0.0f;
#pragma unroll
        for (int c = 0; c < 8; c++) {
            const float2 ft = stab[idx[c]];
            acc0 = fmaf(wgt[c], ft.x, acc0);
            acc1 = fmaf(wgt[c], ft.y, acc1);
        }

        featl[p] = make_float2(acc0, acc1);
    }
}

// ============================ Phase 2: MLP =================================
__global__ __launch_bounds__(P2_THREADS, 1)
void mlp_kernel(const float* __restrict__ x,
                const float* __restrict__ dW0, const float* __restrict__ db0,
                const float* __restrict__ dW1, const float* __restrict__ db1,
                const float* __restrict__ cW0, const float* __restrict__ cb0,
                const float* __restrict__ cW1, const float* __restrict__ cb1,
                const float* __restrict__ cW2, const float* __restrict__ cb2,
                float* __restrict__ out, int B)
{
    __shared__ alignas(16) float sW0 [32 * 64];
    __shared__ alignas(16) float sB0 [64];
    __shared__ alignas(16) float sW1 [64 * 16];
    __shared__ alignas(16) float sB1 [16];
    __shared__ alignas(16) float sC0W[20 * 64];
    __shared__ alignas(16) float sC0B[64];
    __shared__ alignas(16) float sC1Wt[64 * 64];   // transposed [j][k]
    __shared__ alignas(16) float sC1B[64];
    __shared__ alignas(16) float sC2W[64 * 4];
    __shared__ alignas(16) float sC2B[4];

    const int tid = threadIdx.x;
    for (int i = tid; i < 32 * 64; i += P2_THREADS) sW0[i]  = dW0[i];
    for (int i = tid; i < 64 * 16; i += P2_THREADS) sW1[i]  = dW1[i];
    for (int i = tid; i < 19 * 64; i += P2_THREADS) sC0W[i] = cW0[i];
    for (int i = tid; i < 64 * 64; i += P2_THREADS) {
        const int k = i >> 6, j = i & 63;
        sC1Wt[j * 64 + k] = cW1[i];
    }
    for (int i = tid; i < 64; i += P2_THREADS) {
        sB0[i]  = db0[i];
        sC0B[i] = cb0[i];
        sC1B[i] = cb1[i];
        sC2W[i * 4 + 0] = cW2[i * 3 + 0];
        sC2W[i * 4 + 1] = cW2[i * 3 + 1];
        sC2W[i * 4 + 2] = cW2[i * 3 + 2];
        sC2W[i * 4 + 3] = 0.0f;
    }
    if (tid < 16) sB1[tid]  = db1[tid];
    if (tid < 4)  sC2B[tid] = (tid < 3) ? cb2[tid] : 0.0f;
    __syncthreads();

    const int pbase = blockIdx.x * (P2_THREADS * P2_PTS_PER_THREAD) + tid;
    int pt[2];
    pt[0] = pbase;
    pt[1] = pbase + P2_THREADS;
    const bool ok1 = pt[1] < B;
    if (pt[0] >= B) return;
    if (!ok1) pt[1] = pt[0];   // degenerate duplicate, result discarded

    // ---- stage 0: h = db0 + sum_l feat_l @ dW0 rows, packed, 2-pt ILP ----
    u64 hp0[32], hp1[32];
    {
        const u64* b = reinterpret_cast<const u64*>(sB0);
#pragma unroll
        for (int j = 0; j < 32; j++) { hp0[j] = b[j]; hp1[j] = b[j]; }
    }

    float2 f0 = __ldg(&g_feats[pt[0]]);
    float2 f1 = __ldg(&g_feats[pt[1]]);
#pragma unroll
    for (int l = 0; l < L_LEVELS; l++) {
        float2 nf0, nf1;
        if (l + 1 < L_LEVELS) {
            nf0 = __ldg(&g_feats[(size_t)(l + 1) * B + pt[0]]);
            nf1 = __ldg(&g_feats[(size_t)(l + 1) * B + pt[1]]);
        }
        const u64 a00 = pack2(f0.x, f0.x), a01 = pack2(f0.y, f0.y);
        const u64 a10 = pack2(f1.x, f1.x), a11 = pack2(f1.y, f1.y);
        const u64* r0 = reinterpret_cast<const u64*>(&sW0[(2 * l) * 64]);
        const u64* r1 = reinterpret_cast<const u64*>(&sW0[(2 * l + 1) * 64]);
#pragma unroll
        for (int j = 0; j < 32; j++) {
            const u64 w0 = r0[j], w1 = r1[j];
            fma2(hp0[j], a00, w0);
            fma2(hp1[j], a10, w0);
            fma2(hp0[j], a01, w1);
            fma2(hp1[j], a11, w1);
        }
        f0 = nf0; f1 = nf1;
    }

    // ---- layer 1: h2 = relu(h) @ dW1 + db1  (64 -> 16) ----
    u64 hq0[8], hq1[8];
    {
        const u64* b = reinterpret_cast<const u64*>(sB1);
#pragma unroll
        for (int m = 0; m < 8; m++) { hq0[m] = b[m]; hq1[m] = b[m]; }
    }
#pragma unroll
    for (int j2 = 0; j2 < 32; j2++) {
        const float2 v0 = unpack2(hp0[j2]);
        const float2 v1 = unpack2(hp1[j2]);
        const u64 p00 = pack2(fmaxf(v0.x, 0.0f), fmaxf(v0.x, 0.0f));
        const u64 p01 = pack2(fmaxf(v0.y, 0.0f), fmaxf(v0.y, 0.0f));
        const u64 p10 = pack2(fmaxf(v1.x, 0.0f), fmaxf(v1.x, 0.0f));
        const u64 p11 = pack2(fmaxf(v1.y, 0.0f), fmaxf(v1.y, 0.0f));
        const u64* w0 = reinterpret_cast<const u64*>(&sW1[(2 * j2) * 16]);
        const u64* w1 = reinterpret_cast<const u64*>(&sW1[(2 * j2 + 1) * 16]);
#pragma unroll
        for (int m = 0; m < 8; m++) {
            const u64 a = w0[m], b2 = w1[m];
            fma2(hq0[m], p00, a);
            fma2(hq1[m], p10, a);
            fma2(hq0[m], p01, b2);
            fma2(hq1[m], p11, b2);
        }
    }

    float h2a[16], h2b[16];
#pragma unroll
    for (int m = 0; m < 8; m++) {
        const float2 va = unpack2(hq0[m]);
        const float2 vb = unpack2(hq1[m]);
        h2a[2 * m] = va.x; h2a[2 * m + 1] = va.y;
        h2b[2 * m] = vb.x; h2b[2 * m + 1] = vb.y;
    }

    const float dens0 = sigmoidf_fast(h2a[0]);
    const float dens1 = sigmoidf_fast(h2b[0]);

    // ---- cin = [density, relu(h2[1:16]), view] ----
    float cina[19], cinb[19];
    cina[0] = dens0; cinb[0] = dens1;
#pragma unroll
    for (int m = 1; m < 16; m++) {
        cina[m] = fmaxf(h2a[m], 0.0f);
        cinb[m] = fmaxf(h2b[m], 0.0f);
    }
    {
        const float2* xv0 = reinterpret_cast<const float2*>(x) + (size_t)pt[0] * 3;
        const float2* xv1 = reinterpret_cast<const float2*>(x) + (size_t)pt[1] * 3;
        const float2 b1a = __ldg(&xv0[1]); const float2 b2a = __ldg(&xv0[2]);
        const float2 b1b = __ldg(&xv1[1]); const float2 b2b = __ldg(&xv1[2]);
        cina[16] = b1a.y; cina[17] = b2a.x; cina[18] = b2a.y;
        cinb[16] = b1b.y; cinb[17] = b2b.x; cinb[18] = b2b.y;
    }

    // ---- c1 = relu(cin @ cW0 + cb0)  (19 -> 64) ----
    u64 c1p0[32], c1p1[32];
    {
        const u64* b = reinterpret_cast<const u64*>(sC0B);
#pragma unroll
        for (int j = 0; j < 32; j++) { c1p0[j] = b[j]; c1p1[j] = b[j]; }
    }
#pragma unroll
    for (int k = 0; k < 19; k++) {
        const u64 ca = pack2(cina[k], cina[k]);
        const u64 cb = pack2(cinb[k], cinb[k]);
        const u64* wr = reinterpret_cast<const u64*>(&sC0W[k * 64]);
#pragma unroll
        for (int j = 0; j < 32; j++) {
            const u64 w = wr[j];
            fma2(c1p0[j], ca, w);
            fma2(c1p1[j], cb, w);
        }
    }
#pragma unroll
    for (int j = 0; j < 32; j++) {
        float2 va = unpack2(c1p0[j]);
        float2 vb = unpack2(c1p1[j]);
        c1p0[j] = pack2(fmaxf(va.x, 0.0f), fmaxf(va.y, 0.0f));
        c1p1[j] = pack2(fmaxf(vb.x, 0.0f), fmaxf(vb.y, 0.0f));
    }

    // ---- c2 = relu(c1 @ cW1 + cb1) streamed into cW2 (64 -> 64 -> 3) ----
    float col[2][3];
    col[0][0] = sC2B[0]; col[0][1] = sC2B[1]; col[0][2] = sC2B[2];
    col[1][0] = sC2B[0]; col[1][1] = sC2B[1]; col[1][2] = sC2B[2];
#pragma unroll 4
    for (int j = 0; j < 64; j++) {
        u64 apa = 0ULL, apb = 0ULL;
        const u64* wr = reinterpret_cast<const u64*>(&sC1Wt[j * 64]);
#pragma unroll
        for (int k = 0; k < 32; k++) {
            const u64 w = wr[k];
            fma2(apa, c1p0[k], w);
            fma2(apb, c1p1[k], w);
        }
        const float2 va = unpack2(apa);
        const float2 vb = unpack2(apb);
        const float bias = sC1B[j];
        float aa = fmaxf(bias + va.x + va.y, 0.0f);
        float ab = fmaxf(bias + vb.x + vb.y, 0.0f);
        const float4 w2v = *reinterpret_cast<const float4*>(&sC2W[j * 4]);
        col[0][0] = fmaf(aa, w2v.x, col[0][0]);
        col[0][1] = fmaf(aa, w2v.y, col[0][1]);
        col[0][2] = fmaf(aa, w2v.z, col[0][2]);
        col[1][0] = fmaf(ab, w2v.x, col[1][0]);
        col[1][1] = fmaf(ab, w2v.y, col[1][1]);
        col[1][2] = fmaf(ab, w2v.z, col[1][2]);
    }

    reinterpret_cast<float4*>(out)[pt[0]] =
        make_float4(dens0, sigmoidf_fast(col[0][0]), sigmoidf_fast(col[0][1]), sigmoidf_fast(col[0][2]));
    if (ok1) {
        reinterpret_cast<float4*>(out)[pt[1]] =
            make_float4(dens1, sigmoidf_fast(col[1][0]), sigmoidf_fast(col[1][1]), sigmoidf_fast(col[1][2]));
    }
}

} // anonymous namespace

extern "C" void kernel_launch(void* const* d_in, const int* in_sizes, int n_in,
                              void* d_out, int out_size)
{
    const float* x    = (const float*)d_in[0];
    const float* emb  = (const float*)d_in[1];
    const float* dW0  = (const float*)d_in[2];
    const float* db0  = (const float*)d_in[3];
    const float* dW1  = (const float*)d_in[4];
    const float* db1  = (const float*)d_in[5];
    const float* cW0  = (const float*)d_in[6];
    const float* cb0  = (const float*)d_in[7];
    const float* cW1  = (const float*)d_in[8];
    const float* cb1  = (const float*)d_in[9];
    const float* cW2  = (const float*)d_in[10];
    const float* cb2  = (const float*)d_in[11];
    float* out = (float*)d_out;

    const int B = in_sizes[0] / 6;

    NsParams nsp;
    const double g = exp((log(512.0) - log(16.0)) / 15.0);
    for (int i = 0; i < L_LEVELS; i++) {
        nsp.ns[i] = (int)(16.0 * pow(g, (double)i));
    }

    static bool attr_set = false;
    if (!attr_set) {
        cudaFuncSetAttribute(gather_kernel,
                             cudaFuncAttributeMaxDynamicSharedMemorySize,
                             T_SIZE * (int)sizeof(float2));
        attr_set = true;
    }

    const int nb1 = (B + P1_PTS_PER_BLOCK - 1) / P1_PTS_PER_BLOCK;
    dim3 grid1(nb1, L_LEVELS);
    gather_kernel<<<grid1, P1_THREADS, T_SIZE * sizeof(float2)>>>(x, emb, B, nsp);

    const int ptsPerBlock2 = P2_THREADS * P2_PTS_PER_THREAD;
    const int nb2 = (B + ptsPerBlock2 - 1) / ptsPerBlock2;
    mlp_kernel<<<nb2, P2_THREADS>>>(x, dW0, db0, dW1, db1,
                                    cW0, cb0, cW1, cb1, cW2, cb2, out, B);
}